// round 3
// baseline (speedup 1.0000x reference)
#include <cuda_runtime.h>
#include <cuda_bf16.h>

// 8x8 blockwise DCT with output transpose:
//   OUT[v][u] = sum_{k,l} D[u,k] * X[k,l] * D[v,l]
// x: (32, 3, 512, 512) fp32   dct_basis: (8,8) fp32
// FOUR threads per 8x8 block: thread q owns output columns u in [2q, 2q+2).
// t[2][8] = 16 accumulators -> ~40 regs -> 6 CTAs/SM (75% occ ceiling) to
// hide DRAM latency. The 4 sibling threads read the same cache lines (L1
// dedupes); stores remain fully coalesced (256B contiguous per warp-store).

#define IMG_DIM     512
#define NIMG        (32 * 3)
#define BLK_PER_ROW (IMG_DIM / 8)                                 // 64
#define NBLOCKS     (NIMG * BLK_PER_ROW * BLK_PER_ROW)            // 393216
#define SPLIT       4
#define NTHREADS    (NBLOCKS * SPLIT)                             // 1572864
#define TPB         256

__global__ __launch_bounds__(TPB, 6) void dct_blocks_kernel(
    const float* __restrict__ x,
    const float* __restrict__ dct,
    float* __restrict__ out)
{
    __shared__ float Ds[64];   // D row-major:   Ds[v*8+l] = D[v][l]
    __shared__ float Dt[64];   // D transposed:  Dt[k*8+u] = D[u][k]
    if (threadIdx.x < 64) {
        float val = dct[threadIdx.x];
        Ds[threadIdx.x] = val;
        int u = threadIdx.x >> 3;
        int k = threadIdx.x & 7;
        Dt[k * 8 + u] = val;
    }
    __syncthreads();

    int g    = blockIdx.x * TPB + threadIdx.x;  // 0 .. NTHREADS-1
    int q    = g & (SPLIT - 1);                 // which column pair
    int p    = g >> 2;                          // block index
    int bx   = p & (BLK_PER_ROW - 1);
    int tmp  = p >> 6;
    int by   = tmp & (BLK_PER_ROW - 1);
    int img  = tmp >> 6;
    int uo   = q * 2;

    size_t base = ((size_t)img * IMG_DIM + (size_t)by * 8) * IMG_DIM + (size_t)bx * 8;
    const float* src = x + base;
    float*       dst = out + base;

    // Stage 1: t[u2][l] = sum_k D[uo+u2, k] * X[k, l]   (stream X rows)
    float t[2][8];
    #pragma unroll
    for (int u2 = 0; u2 < 2; ++u2)
        #pragma unroll
        for (int l = 0; l < 8; ++l)
            t[u2][l] = 0.0f;

    #pragma unroll
    for (int k = 0; k < 8; ++k) {
        float4 a = *(const float4*)(src + (size_t)k * IMG_DIM);
        float4 b = *(const float4*)(src + (size_t)k * IMG_DIM + 4);
        float xr[8] = {a.x, a.y, a.z, a.w, b.x, b.y, b.z, b.w};
        float2 dk = *(const float2*)(Dt + k * 8 + uo);  // D[uo..uo+1][k]
        #pragma unroll
        for (int l = 0; l < 8; ++l) {
            t[0][l] = fmaf(dk.x, xr[l], t[0][l]);
            t[1][l] = fmaf(dk.y, xr[l], t[1][l]);
        }
    }

    // Stage 2: OUT[v][uo+u2] = sum_l t[u2][l] * D[v, l]; emit per output row v.
    #pragma unroll
    for (int v = 0; v < 8; ++v) {
        float4 d0 = *(const float4*)(Ds + v * 8);
        float4 d1 = *(const float4*)(Ds + v * 8 + 4);
        float dv[8] = {d0.x, d0.y, d0.z, d0.w, d1.x, d1.y, d1.z, d1.w};
        float s0 = 0.0f, s1 = 0.0f;
        #pragma unroll
        for (int l = 0; l < 8; ++l) {
            s0 = fmaf(t[0][l], dv[l], s0);
            s1 = fmaf(t[1][l], dv[l], s1);
        }
        *(float2*)(dst + (size_t)v * IMG_DIM + uo) = make_float2(s0, s1);
    }
}

extern "C" void kernel_launch(void* const* d_in, const int* in_sizes, int n_in,
                              void* d_out, int out_size)
{
    const float* x   = (const float*)d_in[0];
    const float* dct = (const float*)d_in[1];
    float*       out = (float*)d_out;

    dct_blocks_kernel<<<NTHREADS / TPB, TPB>>>(x, dct, out);
}

// round 4
// speedup vs baseline: 1.1736x; 1.1736x over previous
#include <cuda_runtime.h>
#include <cuda_bf16.h>

// 8x8 blockwise DCT with output transpose:
//   OUT[v][u] = sum_{k,l} D[u,k] * X[k,l] * D[v,l]
// x: (32, 3, 512, 512) fp32   dct_basis: (8,8) fp32
//
// One CTA per 8-row x 512-col strip (contiguous 16KB in gmem). Phase 1:
// cooperative fully-coalesced load into smem (each global line requested
// exactly once -> kills the L1tex request duplication that bound R3).
// Phase 2: 4 threads per 8x8 block compute 2 output columns each from smem
// (lane-broadcast is free on the crossbar), store coalesced float2 direct.

#define IMG_DIM     512
#define NIMG        (32 * 3)
#define STRIPS      (NIMG * (IMG_DIM / 8))     // 6144
#define STRIP_FLOATS (8 * IMG_DIM)             // 4096
#define TPB         256

__global__ __launch_bounds__(TPB, 6) void dct_blocks_kernel(
    const float* __restrict__ x,
    const float* __restrict__ dct,
    float* __restrict__ out)
{
    __shared__ float S[STRIP_FLOATS];   // the 8x512 strip
    __shared__ float Ds[64];            // D row-major:  Ds[v*8+l] = D[v][l]
    __shared__ float Dt[64];            // D transposed: Dt[k*8+u] = D[u][k]

    if (threadIdx.x < 64) {
        float val = dct[threadIdx.x];
        Ds[threadIdx.x] = val;
        int u = threadIdx.x >> 3;
        int k = threadIdx.x & 7;
        Dt[k * 8 + u] = val;
    }

    size_t base = (size_t)blockIdx.x * STRIP_FLOATS;
    const float4* src4 = (const float4*)(x + base);
    float*        dst  = out + base;

    // Phase 1: coalesced strip load, every 128B line fetched exactly once.
    float4* S4 = (float4*)S;
    #pragma unroll
    for (int i = 0; i < 4; ++i) {
        int idx = threadIdx.x + i * TPB;   // 0 .. 1023
        S4[idx] = src4[idx];
    }
    __syncthreads();

    // Phase 2: thread (bx, q) computes output columns uo..uo+1 of block bx.
    int q  = threadIdx.x & 3;
    int bx = threadIdx.x >> 2;
    int uo = q * 2;

    // Stage 1: t[u2][l] = sum_k D[uo+u2, k] * X[k, l]
    float t0[8], t1[8];
    #pragma unroll
    for (int l = 0; l < 8; ++l) { t0[l] = 0.0f; t1[l] = 0.0f; }

    #pragma unroll
    for (int k = 0; k < 8; ++k) {
        const float* row = S + k * IMG_DIM + bx * 8;
        float4 a = *(const float4*)(row);
        float4 b = *(const float4*)(row + 4);
        float xr[8] = {a.x, a.y, a.z, a.w, b.x, b.y, b.z, b.w};
        float2 dk = *(const float2*)(Dt + k * 8 + uo);  // D[uo..uo+1][k]
        #pragma unroll
        for (int l = 0; l < 8; ++l) {
            t0[l] = fmaf(dk.x, xr[l], t0[l]);
            t1[l] = fmaf(dk.y, xr[l], t1[l]);
        }
    }

    // Stage 2: OUT[v][uo+u2] = sum_l t[u2][l] * D[v, l]; coalesced float2 store.
    #pragma unroll
    for (int v = 0; v < 8; ++v) {
        float4 d0 = *(const float4*)(Ds + v * 8);
        float4 d1 = *(const float4*)(Ds + v * 8 + 4);
        float dv[8] = {d0.x, d0.y, d0.z, d0.w, d1.x, d1.y, d1.z, d1.w};
        float s0 = 0.0f, s1 = 0.0f;
        #pragma unroll
        for (int l = 0; l < 8; ++l) {
            s0 = fmaf(t0[l], dv[l], s0);
            s1 = fmaf(t1[l], dv[l], s1);
        }
        *(float2*)(dst + (size_t)v * IMG_DIM + bx * 8 + uo) = make_float2(s0, s1);
    }
}

extern "C" void kernel_launch(void* const* d_in, const int* in_sizes, int n_in,
                              void* d_out, int out_size)
{
    const float* x   = (const float*)d_in[0];
    const float* dct = (const float*)d_in[1];
    float*       out = (float*)d_out;

    dct_blocks_kernel<<<STRIPS, TPB>>>(x, dct, out);
}